// round 14
// baseline (speedup 1.0000x reference)
#include <cuda_runtime.h>

#define N_USR 50000
#define N_ENT 100000
#define DD 64
#define NE 1000000
#define NEI 500000

// ---- scratch (device globals; no allocation allowed) ----
__device__ __align__(16) float g_Q[N_ENT * DD];       // P = src @ W_Q (compact, for q reads)
__device__ __align__(16) float g_PV[N_ENT * 128];     // interleaved {P2j,P2j+1,v2j,v2j+1}
__device__ __align__(16) float g_eL1[N_ENT * DD];     // entity emb after layer 1
__device__ __align__(16) float g_esum[N_ENT * DD];    // running sum of entity embs
__device__ __align__(16) float g_agg[N_ENT * DD];     // per-layer accumulator
__device__ __align__(16) float g_den[N_ENT * 2];      // softmax denominators
// sorted edge stream (by head)
__device__ int   g_cnt[N_ENT];
__device__ int   g_cur[N_ENT];
__device__ uint2 g_edge[NE];     // {tail | (etype-1)<<17, head}

// ---- init: esum = entity_emb; d_out user region = user_emb; zero accum + hist ----
__global__ void k_init(const float4* __restrict__ ue, const float4* __restrict__ ee,
                       float4* __restrict__ uout) {
    int i = blockIdx.x * blockDim.x + threadIdx.x;
    if (i < N_ENT * DD / 4) {
        ((float4*)g_esum)[i] = ee[i];
        ((float4*)g_agg)[i] = make_float4(0.f, 0.f, 0.f, 0.f);
    }
    if (i < N_USR * DD / 4) uout[i] = ue[i];
    if (i < N_ENT) g_cnt[i] = 0;
    if (i < N_ENT * 2 / 4)
        ((float4*)g_den)[i] = make_float4(0.f, 0.f, 0.f, 0.f);
}

// ---- histogram of edge heads ----
__global__ void k_hist(const int* __restrict__ head) {
    int e = blockIdx.x * blockDim.x + threadIdx.x;
    if (e < NE) atomicAdd(&g_cnt[__ldg(&head[e])], 1);
}

// ---- exclusive scan over entity counts (single block) ----
__global__ void k_scan() {
    __shared__ int s[1024];
    int tid = threadIdx.x;
    const int chunk = (N_ENT + 1023) / 1024;
    int b = tid * chunk, e = min(b + chunk, N_ENT);
    int sum = 0;
    for (int i = b; i < e; i++) sum += g_cnt[i];
    s[tid] = sum;
    __syncthreads();
    for (int off = 1; off < 1024; off <<= 1) {
        int v = (tid >= off) ? s[tid - off] : 0;
        __syncthreads();
        s[tid] += v;
        __syncthreads();
    }
    int run = (tid == 0) ? 0 : s[tid - 1];
    for (int i = b; i < e; i++) {
        g_cur[i] = run;
        run += g_cnt[i];
    }
}

// ---- scatter edges into head-sorted order ----
__global__ void k_fill(const int* __restrict__ head, const int* __restrict__ tail,
                       const int* __restrict__ et) {
    int e = blockIdx.x * blockDim.x + threadIdx.x;
    if (e >= NE) return;
    int h = __ldg(&head[e]);
    int pos = atomicAdd(&g_cur[h], 1);
    g_edge[pos] = make_uint2((unsigned)__ldg(&tail[e]) |
                             ((unsigned)(__ldg(&et[e]) - 1) << 17), (unsigned)h);
}

// ---- Q + PV = {src @ W_Q, src}; warp handles 4 rows ----
__global__ void k_gemm(const float* __restrict__ ein, int layer,
                       const float* __restrict__ W) {
    const float* src = (layer == 0) ? ein : g_eL1;
    __shared__ float sW[DD * DD];
    for (int i = threadIdx.x; i < DD * DD; i += 256) sW[i] = W[i];
    __syncthreads();
    int warp = threadIdx.x >> 5, lane = threadIdx.x & 31;
    int r0 = (blockIdx.x * 8 + warp) * 4;
    if (r0 >= N_ENT) return;
    const float* e0 = &src[(size_t)r0 * DD];
    float acc[8] = {0.f, 0.f, 0.f, 0.f, 0.f, 0.f, 0.f, 0.f};
    #pragma unroll 4
    for (int k = 0; k < DD; k += 4) {
        float4 a[4];
        #pragma unroll
        for (int rr = 0; rr < 4; rr++) a[rr] = *(const float4*)&e0[rr * DD + k];
        #pragma unroll
        for (int j = 0; j < 4; j++) {
            float2 wv = *(const float2*)&sW[(k + j) * DD + lane * 2];
            #pragma unroll
            for (int rr = 0; rr < 4; rr++) {
                float av = (j == 0) ? a[rr].x : (j == 1) ? a[rr].y : (j == 2) ? a[rr].z : a[rr].w;
                acc[rr * 2]     += av * wv.x;
                acc[rr * 2 + 1] += av * wv.y;
            }
        }
    }
    #pragma unroll
    for (int rr = 0; rr < 4; rr++) {
        float2 v = *(const float2*)&e0[rr * DD + lane * 2];
        *(float2*)&g_Q[(size_t)(r0 + rr) * DD + lane * 2] =
            make_float2(acc[rr * 2], acc[rr * 2 + 1]);
        *(float4*)&g_PV[(size_t)(r0 + rr) * 128 + lane * 4] =
            make_float4(acc[rr * 2], acc[rr * 2 + 1], v.x, v.y);
    }
}

// ---- edge-parallel fused pass over head-sorted edges:
//      16 lanes/edge, lane owns dims 4l..4l+3; lanes 0-7 head0, 8-15 head1.
//      score -> exp -> den RED + float4 RED of ex*(v.rel) into g_agg ----
__global__ void k_edge(const float* __restrict__ rel) {
    __shared__ float s_rel[16 * DD];
    for (int i = threadIdx.x; i < 16 * DD; i += blockDim.x) s_rel[i] = rel[i];
    __syncthreads();
    int gid = blockIdx.x * blockDim.x + threadIdx.x;
    int e = gid >> 4, hl = gid & 15;
    if (e >= NE) return;
    uint2 ed = __ldg(&g_edge[e]);
    int t = ed.x & 0x1FFFF, r = ed.x >> 17, h = (int)ed.y;
    float4 q   = *(const float4*)&g_Q[(size_t)h * DD + hl * 4];     // L1-hot (sorted)
    float4 pv0 = *(const float4*)&g_PV[(size_t)t * 128 + hl * 8];    // {P4l,P4l+1,v4l,v4l+1}
    float4 pv1 = *(const float4*)&g_PV[(size_t)t * 128 + hl * 8 + 4];// {P4l+2,..}
    float4 rl  = *(const float4*)&s_rel[r * DD + hl * 4];
    float p = q.x * pv0.x * rl.x + q.y * pv0.y * rl.y +
              q.z * pv1.x * rl.z + q.w * pv1.y * rl.w;
    p += __shfl_xor_sync(0xffffffffu, p, 1);
    p += __shfl_xor_sync(0xffffffffu, p, 2);
    p += __shfl_xor_sync(0xffffffffu, p, 4);
    const float inv = 0.17677669529663688f;  // 1/sqrt(32)
    float ex = __expf(p * inv);
    if ((hl & 7) == 0)
        atomicAdd(&g_den[h * 2 + (hl >> 3)], ex);
    float4 o = make_float4(ex * pv0.z * rl.x, ex * pv0.w * rl.y,
                           ex * pv1.z * rl.z, ex * pv1.w * rl.w);
    atomicAdd((float4*)&g_agg[(size_t)h * DD + hl * 4], o);
}

// ---- user aggregation: uout += w * src[item]  (16 lanes per inter-edge) ----
__global__ void k_user(const int* __restrict__ iu, const int* __restrict__ ii,
                       const float* __restrict__ w, const float* __restrict__ ein,
                       int layer, float* __restrict__ uout) {
    const float* src = (layer == 0) ? ein : g_eL1;
    int gid = blockIdx.x * blockDim.x + threadIdx.x;
    int e = gid >> 4, hl = gid & 15;
    if (e >= NEI) return;
    int u = __ldg(&iu[e]), it = __ldg(&ii[e]);
    float ww = __ldg(&w[e]);
    float4 v = *(const float4*)&src[(size_t)it * DD + hl * 4];
    atomicAdd((float4*)&uout[(size_t)u * DD + hl * 4],
              make_float4(v.x * ww, v.y * ww, v.z * ww, v.w * ww));
}

// ---- per-row finalize: agg/den -> L2 norm; esum; re-zero agg/den;
//      layer 1 writes final entity mean straight to d_out ----
__global__ void k_update(int layer, float* __restrict__ eout) {
    int row = (blockIdx.x * blockDim.x + threadIdx.x) >> 5;
    int lane = threadIdx.x & 31;
    if (row >= N_ENT) return;
    float2* ap = (float2*)&g_agg[(size_t)row * DD + lane * 2];
    float2 a = *ap;
    *ap = make_float2(0.f, 0.f);
    float d = g_den[row * 2 + (lane >> 4)];
    if (lane < 2) g_den[row * 2 + lane] = 0.f;
    float invd = (d > 0.f) ? (1.f / d) : 0.f;
    a.x *= invd; a.y *= invd;
    float ss = a.x * a.x + a.y * a.y;
    #pragma unroll
    for (int m = 1; m < 32; m <<= 1) ss += __shfl_xor_sync(0xffffffffu, ss, m);
    float nrm = 1.f / fmaxf(sqrtf(ss), 1e-12f);
    float ex0 = a.x * nrm, ey0 = a.y * nrm;
    float2* es = (float2*)&g_esum[(size_t)row * DD + lane * 2];
    float2 o = *es;
    if (layer == 0) {
        *(float2*)&g_eL1[(size_t)row * DD + lane * 2] = make_float2(ex0, ey0);
        *es = make_float2(o.x + ex0, o.y + ey0);
    } else {
        const float th = 1.f / 3.f;
        *(float2*)&eout[(size_t)row * DD + lane * 2] =
            make_float2((o.x + ex0) * th, (o.y + ey0) * th);
    }
}

// ---- scale user output by 1/3 ----
__global__ void k_ufinal(float4* __restrict__ uout) {
    int i = blockIdx.x * blockDim.x + threadIdx.x;
    if (i < N_USR * DD / 4) {
        const float th = 1.f / 3.f;
        float4 v = uout[i];
        uout[i] = make_float4(v.x * th, v.y * th, v.z * th, v.w * th);
    }
}

extern "C" void kernel_launch(void* const* d_in, const int* in_sizes, int n_in,
                              void* d_out, int out_size) {
    // inputs: layers_num, user_emb, entity_emb, inter_edge, inter_edge_w,
    //         edge_index, edge_type, relation_emb, W_Q
    const float* user_emb = (const float*)d_in[1];
    const float* ent_emb  = (const float*)d_in[2];
    const int*   inter    = (const int*)d_in[3];
    const float* iw       = (const float*)d_in[4];
    const int*   eidx     = (const int*)d_in[5];
    const int*   etype    = (const int*)d_in[6];
    const float* rel      = (const float*)d_in[7];
    const float* WQ       = (const float*)d_in[8];
    const int* head = eidx;
    const int* tail = eidx + NE;
    const int* iu = inter;
    const int* ii = inter + NEI;
    float* out = (float*)d_out;
    float* out_ent = out + (size_t)N_USR * DD;

    const int T = 256;
    const int nE4 = N_ENT * DD / 4;  // 1.6M

    k_init<<<(nE4 + T - 1) / T, T>>>((const float4*)user_emb, (const float4*)ent_emb,
                                     (float4*)out);
    k_hist<<<(NE + T - 1) / T, T>>>(head);
    k_scan<<<1, 1024>>>();
    k_fill<<<(NE + T - 1) / T, T>>>(head, tail, etype);
    for (int l = 0; l < 2; l++) {
        k_gemm<<<N_ENT / 32, 256>>>(ent_emb, l, WQ);
        k_edge<<<NE * 16 / T, T>>>(rel);                     // launch #6: ncu target
        k_user<<<NEI * 16 / T, T>>>(iu, ii, iw, ent_emb, l, out);
        k_update<<<(N_ENT * 32 + T - 1) / T, T>>>(l, out_ent);
    }
    k_ufinal<<<(N_USR * DD / 4 + T - 1) / T, T>>>((float4*)out);
}

// round 15
// speedup vs baseline: 1.3047x; 1.3047x over previous
#include <cuda_runtime.h>
#include <cuda_bf16.h>

#define N_USR 50000
#define N_ENT 100000
#define DD 64
#define NE 1000000
#define NEI 500000

// ---- scratch (device globals; no allocation allowed) ----
// g_KV row (96 floats = 384 B): [0:32)  = P row as 64 bf16 (score operand)
//                               [32:96) = v row as 64 f32  (value operand)
__device__ __align__(16) float g_KV[N_ENT * 96];
__device__ __align__(16) float g_eL1[N_ENT * DD];     // entity emb after layer 1
__device__ __align__(16) float g_esum[N_ENT * DD];    // running sum of entity embs
__device__ __align__(16) float g_agg[N_ENT * DD];     // per-layer accumulator
__device__ __align__(16) float g_den[N_ENT * 2];      // softmax denominators

// ---- init: esum = entity_emb; d_out user region = user_emb; zero agg/den ----
__global__ void k_init(const float4* __restrict__ ue, const float4* __restrict__ ee,
                       float4* __restrict__ uout) {
    int i = blockIdx.x * blockDim.x + threadIdx.x;
    if (i < N_ENT * DD / 4) {
        ((float4*)g_esum)[i] = ee[i];
        ((float4*)g_agg)[i] = make_float4(0.f, 0.f, 0.f, 0.f);
    }
    if (i < N_USR * DD / 4) uout[i] = ue[i];
    if (i < N_ENT * 2 / 4)
        ((float4*)g_den)[i] = make_float4(0.f, 0.f, 0.f, 0.f);
}

// ---- KV = {bf16(src @ W_Q), f32 src}; warp handles 4 rows, lane owns 2 cols ----
__global__ void k_gemm(const float* __restrict__ ein, int layer,
                       const float* __restrict__ W) {
    const float* src = (layer == 0) ? ein : g_eL1;
    __shared__ float sW[DD * DD];
    for (int i = threadIdx.x; i < DD * DD; i += 256) sW[i] = W[i];
    __syncthreads();
    int warp = threadIdx.x >> 5, lane = threadIdx.x & 31;
    int r0 = (blockIdx.x * 8 + warp) * 4;
    if (r0 >= N_ENT) return;
    const float* e0 = &src[(size_t)r0 * DD];
    float acc[8] = {0.f, 0.f, 0.f, 0.f, 0.f, 0.f, 0.f, 0.f};
    #pragma unroll 4
    for (int k = 0; k < DD; k += 4) {
        float4 a[4];
        #pragma unroll
        for (int rr = 0; rr < 4; rr++) a[rr] = *(const float4*)&e0[rr * DD + k];
        #pragma unroll
        for (int j = 0; j < 4; j++) {
            float2 wv = *(const float2*)&sW[(k + j) * DD + lane * 2];
            #pragma unroll
            for (int rr = 0; rr < 4; rr++) {
                float av = (j == 0) ? a[rr].x : (j == 1) ? a[rr].y : (j == 2) ? a[rr].z : a[rr].w;
                acc[rr * 2]     += av * wv.x;
                acc[rr * 2 + 1] += av * wv.y;
            }
        }
    }
    #pragma unroll
    for (int rr = 0; rr < 4; rr++) {
        size_t base = (size_t)(r0 + rr) * 96;
        __nv_bfloat162 pb = __float22bfloat162_rn(make_float2(acc[rr * 2], acc[rr * 2 + 1]));
        *(__nv_bfloat162*)&g_KV[base + lane] = pb;                 // K region (bf16)
        float2 v = *(const float2*)&e0[rr * DD + lane * 2];
        *(float2*)&g_KV[base + 32 + lane * 2] = v;                 // v region (f32)
    }
}

// ---- edge-parallel fused pass (UNSORTED -> spread atomics):
//      16 lanes/edge, lane hl owns dims 4hl..4hl+3; lanes 0-7 head0, 8-15 head1.
//      score(bf16 ops) -> exp -> den RED + float4 RED of ex*(v.rel) ----
__global__ void k_edge(const int* __restrict__ head, const int* __restrict__ tail,
                       const int* __restrict__ et, const float* __restrict__ rel) {
    __shared__ float s_rel[16 * DD];
    for (int i = threadIdx.x; i < 16 * DD; i += blockDim.x) s_rel[i] = rel[i];
    __syncthreads();
    int gid = blockIdx.x * blockDim.x + threadIdx.x;
    int e = gid >> 4, hl = gid & 15;
    if (e >= NE) return;
    int h = __ldg(&head[e]), t = __ldg(&tail[e]), r = __ldg(&et[e]) - 1;
    // q (bf16, 8 B/lane) from head row's K region
    uint2 qb = __ldg((const uint2*)&g_KV[(size_t)h * 96 + hl * 2]);
    // k (bf16, 8 B/lane) + v (f32, 16 B/lane) from tail row
    uint2 kb = __ldg((const uint2*)&g_KV[(size_t)t * 96 + hl * 2]);
    float4 v = __ldg((const float4*)&g_KV[(size_t)t * 96 + 32 + hl * 4]);
    float4 rl = *(const float4*)&s_rel[r * DD + hl * 4];
    float2 q01 = __bfloat1622float2(*(__nv_bfloat162*)&qb.x);
    float2 q23 = __bfloat1622float2(*(__nv_bfloat162*)&qb.y);
    float2 k01 = __bfloat1622float2(*(__nv_bfloat162*)&kb.x);
    float2 k23 = __bfloat1622float2(*(__nv_bfloat162*)&kb.y);
    float p = q01.x * k01.x * rl.x + q01.y * k01.y * rl.y +
              q23.x * k23.x * rl.z + q23.y * k23.y * rl.w;
    p += __shfl_xor_sync(0xffffffffu, p, 1);
    p += __shfl_xor_sync(0xffffffffu, p, 2);
    p += __shfl_xor_sync(0xffffffffu, p, 4);
    const float inv = 0.17677669529663688f;  // 1/sqrt(32)
    float ex = __expf(p * inv);
    if ((hl & 7) == 0)
        atomicAdd(&g_den[h * 2 + (hl >> 3)], ex);
    float4 o = make_float4(ex * v.x * rl.x, ex * v.y * rl.y,
                           ex * v.z * rl.z, ex * v.w * rl.w);
    atomicAdd((float4*)&g_agg[(size_t)h * DD + hl * 4], o);
}

// ---- user aggregation: uout += w * src[item]  (16 lanes per inter-edge) ----
__global__ void k_user(const int* __restrict__ iu, const int* __restrict__ ii,
                       const float* __restrict__ w, const float* __restrict__ ein,
                       int layer, float* __restrict__ uout) {
    const float* src = (layer == 0) ? ein : g_eL1;
    int gid = blockIdx.x * blockDim.x + threadIdx.x;
    int e = gid >> 4, hl = gid & 15;
    if (e >= NEI) return;
    int u = __ldg(&iu[e]), it = __ldg(&ii[e]);
    float ww = __ldg(&w[e]);
    float4 v = *(const float4*)&src[(size_t)it * DD + hl * 4];
    atomicAdd((float4*)&uout[(size_t)u * DD + hl * 4],
              make_float4(v.x * ww, v.y * ww, v.z * ww, v.w * ww));
}

// ---- per-row finalize: agg/den -> L2 norm; esum; re-zero agg/den;
//      layer 1 writes final entity mean straight to d_out ----
__global__ void k_update(int layer, float* __restrict__ eout) {
    int row = (blockIdx.x * blockDim.x + threadIdx.x) >> 5;
    int lane = threadIdx.x & 31;
    if (row >= N_ENT) return;
    float2* ap = (float2*)&g_agg[(size_t)row * DD + lane * 2];
    float2 a = *ap;
    *ap = make_float2(0.f, 0.f);
    float d = g_den[row * 2 + (lane >> 4)];
    if (lane < 2) g_den[row * 2 + lane] = 0.f;
    float invd = (d > 0.f) ? (1.f / d) : 0.f;
    a.x *= invd; a.y *= invd;
    float ss = a.x * a.x + a.y * a.y;
    #pragma unroll
    for (int m = 1; m < 32; m <<= 1) ss += __shfl_xor_sync(0xffffffffu, ss, m);
    float nrm = 1.f / fmaxf(sqrtf(ss), 1e-12f);
    float ex0 = a.x * nrm, ey0 = a.y * nrm;
    float2* es = (float2*)&g_esum[(size_t)row * DD + lane * 2];
    float2 o = *es;
    if (layer == 0) {
        *(float2*)&g_eL1[(size_t)row * DD + lane * 2] = make_float2(ex0, ey0);
        *es = make_float2(o.x + ex0, o.y + ey0);
    } else {
        const float th = 1.f / 3.f;
        *(float2*)&eout[(size_t)row * DD + lane * 2] =
            make_float2((o.x + ex0) * th, (o.y + ey0) * th);
    }
}

// ---- scale user output by 1/3 ----
__global__ void k_ufinal(float4* __restrict__ uout) {
    int i = blockIdx.x * blockDim.x + threadIdx.x;
    if (i < N_USR * DD / 4) {
        const float th = 1.f / 3.f;
        float4 v = uout[i];
        uout[i] = make_float4(v.x * th, v.y * th, v.z * th, v.w * th);
    }
}

extern "C" void kernel_launch(void* const* d_in, const int* in_sizes, int n_in,
                              void* d_out, int out_size) {
    // inputs: layers_num, user_emb, entity_emb, inter_edge, inter_edge_w,
    //         edge_index, edge_type, relation_emb, W_Q
    const float* user_emb = (const float*)d_in[1];
    const float* ent_emb  = (const float*)d_in[2];
    const int*   inter    = (const int*)d_in[3];
    const float* iw       = (const float*)d_in[4];
    const int*   eidx     = (const int*)d_in[5];
    const int*   etype    = (const int*)d_in[6];
    const float* rel      = (const float*)d_in[7];
    const float* WQ       = (const float*)d_in[8];
    const int* head = eidx;
    const int* tail = eidx + NE;
    const int* iu = inter;
    const int* ii = inter + NEI;
    float* out = (float*)d_out;
    float* out_ent = out + (size_t)N_USR * DD;

    const int T = 256;
    const int nE4 = N_ENT * DD / 4;  // 1.6M

    k_init<<<(nE4 + T - 1) / T, T>>>((const float4*)user_emb, (const float4*)ent_emb,
                                     (float4*)out);
    for (int l = 0; l < 2; l++) {
        k_gemm<<<N_ENT / 32, 256>>>(ent_emb, l, WQ);
        k_edge<<<NE * 16 / T, T>>>(head, tail, etype, rel);
        k_user<<<NEI * 16 / T, T>>>(iu, ii, iw, ent_emb, l, out);
        k_update<<<(N_ENT * 32 + T - 1) / T, T>>>(l, out_ent);
    }
    k_ufinal<<<(N_USR * DD / 4 + T - 1) / T, T>>>((float4*)out);
}